// round 15
// baseline (speedup 1.0000x reference)
#include <cuda_runtime.h>
#include <cuda_fp16.h>
#include <cstdint>
#include <math.h>

#define BB 128
#define TT 256
#define CC 384
#define HH 4
#define HSS 64
#define LL 6
#define VV 65
#define FFF 1536
#define NT (BB*TT)
#define HQ (HH*HSS)

#define WSZ 1572864
#define W_QKV 0
#define W_PROJ 294912
#define W_FF1 393216
#define W_FF2 983040

__device__ float g_x[NT*CC];          // fp32 residual
__device__ __half g_qkvh[NT*3*HQ];    // q|k|v fp16
__device__ __half g_a[NT*HQ];         // attention output (stride HQ)
__device__ __half g_an[NT*CC];        // LN output (stride CC) - GEMM A operand
__device__ __half g_h[NT*FFF];        // FF hidden
__device__ __half g_w[LL*WSZ];        // fp16 weights [l][n][k]
__device__ float g_wlmT[VV*CC];
__device__ float g_nll[NT];

// ---------- PTX helpers ----------
__device__ __forceinline__ uint32_t s2u(const void* p) {
    uint32_t a;
    asm("{ .reg .u64 t; cvta.to.shared.u64 t, %1; cvt.u32.u64 %0, t; }" : "=r"(a) : "l"(p));
    return a;
}
#define CPA16(d,s) asm volatile("cp.async.cg.shared.global [%0], [%1], 16;" :: "r"(d), "l"(s))
#define CPCOMMIT() asm volatile("cp.async.commit_group;" ::: "memory")
#define CPWAIT0()  asm volatile("cp.async.wait_group 0;" ::: "memory")
#define CPWAIT1()  asm volatile("cp.async.wait_group 1;" ::: "memory")

#define LDSM4(r, a) \
    asm volatile("ldmatrix.sync.aligned.m8n8.x4.shared.b16 {%0,%1,%2,%3}, [%4];" \
        : "=r"((r)[0]), "=r"((r)[1]), "=r"((r)[2]), "=r"((r)[3]) : "r"(a))

#define LDSMT4(r, a) \
    asm volatile("ldmatrix.sync.aligned.m8n8.x4.trans.shared.b16 {%0,%1,%2,%3}, [%4];" \
        : "=r"((r)[0]), "=r"((r)[1]), "=r"((r)[2]), "=r"((r)[3]) : "r"(a))

#define MMAH16816(d, a, b0, b1) \
    asm volatile("mma.sync.aligned.m16n8k16.row.col.f32.f16.f16.f32 " \
        "{%0,%1,%2,%3}, {%4,%5,%6,%7}, {%8,%9}, {%0,%1,%2,%3};" \
        : "+f"((d)[0]), "+f"((d)[1]), "+f"((d)[2]), "+f"((d)[3]) \
        : "r"((a)[0]), "r"((a)[1]), "r"((a)[2]), "r"((a)[3]), "r"(b0), "r"(b1))

__device__ __forceinline__ uint32_t packh2(float a, float b) {
    __half2 h = __halves2half2(__float2half_rn(a), __float2half_rn(b));
    return *(uint32_t*)&h;
}

// ---------- shared GEMM building blocks ----------
__device__ __forceinline__ void load_chunk(uint32_t base, const __half* A, const __half* B,
                                           int K, int bm, int bn, int k0, int tid) {
    #pragma unroll
    for (int i = 0; i < 4; i++) {
        int u = tid + (i << 8);
        int row = u >> 3, kc = u & 7;
        uint32_t d = (uint32_t)(row*128) + ((((uint32_t)kc) ^ (uint32_t)(row & 7)) << 4);
        CPA16(base + d,          (const char*)(A + (size_t)(bm + row) * K + k0) + kc*16);
        CPA16(base + 16384u + d, (const char*)(B + (size_t)(bn + row) * K + k0) + kc*16);
    }
    CPCOMMIT();
}

__device__ __forceinline__ void compute_chunk(uint32_t ab, uint32_t bb,
                                              float (&acc)[4][4][4],
                                              int wm, int wn, int lr, int lh) {
    #pragma unroll
    for (int s = 0; s < 4; s++) {
        uint32_t Bf[2][4];
        #pragma unroll
        for (int bt = 0; bt < 2; bt++) {
            int row = wn*32 + bt*16 + lr;
            uint32_t d = (uint32_t)(row*128) +
                ((((uint32_t)(2*s + lh)) ^ (uint32_t)(row & 7)) << 4);
            LDSM4(Bf[bt], bb + d);
        }
        uint32_t Af[2][4];
        {
            int row = wm*64 + lr;
            uint32_t d = (uint32_t)(row*128) +
                ((((uint32_t)(2*s + lh)) ^ (uint32_t)(row & 7)) << 4);
            LDSM4(Af[0], ab + d);
        }
        #pragma unroll
        for (int mt = 0; mt < 4; mt++) {
            if (mt < 3) {
                int row = wm*64 + (mt+1)*16 + lr;
                uint32_t d = (uint32_t)(row*128) +
                    ((((uint32_t)(2*s + lh)) ^ (uint32_t)(row & 7)) << 4);
                LDSM4(Af[(mt+1) & 1], ab + d);
            }
            const uint32_t* Ac = Af[mt & 1];
            #pragma unroll
            for (int nt = 0; nt < 4; nt++) {
                int g = nt >> 1, j = nt & 1;
                MMAH16816(acc[mt][nt], Ac, Bf[g][j], Bf[g][j+2]);
            }
        }
    }
}

__device__ __forceinline__ void epi_resid(float (&acc)[4][4][4], const float* bias,
                                          float* px, float* rsum, float* rsum2,
                                          int bm, int bn, int wm, int wn, int lane) {
    const int r0 = lane >> 2, c2 = (lane & 3) * 2;
    #pragma unroll
    for (int mt = 0; mt < 4; mt++) {
        #pragma unroll
        for (int half = 0; half < 2; half++) {
            int rl = wm*64 + mt*16 + r0 + half*8;
            int m = bm + rl;
            float ps = 0.f, ps2 = 0.f;
            #pragma unroll
            for (int nt = 0; nt < 4; nt++) {
                int col = bn + wn*32 + nt*8 + c2;
                float v0 = acc[mt][nt][2*half]   + bias[col];
                float v1 = acc[mt][nt][2*half+1] + bias[col+1];
                float2 t = *(const float2*)(px + (size_t)m * CC + col);
                v0 += t.x; v1 += t.y;
                *(float2*)(px + (size_t)m * CC + col) = make_float2(v0, v1);
                ps  += v0 + v1;
                ps2 += v0*v0 + v1*v1;
                acc[mt][nt][2*half] = 0.f;
                acc[mt][nt][2*half+1] = 0.f;
            }
            ps  += __shfl_xor_sync(0xFFFFFFFFu, ps,  1);
            ps  += __shfl_xor_sync(0xFFFFFFFFu, ps,  2);
            ps2 += __shfl_xor_sync(0xFFFFFFFFu, ps2, 1);
            ps2 += __shfl_xor_sync(0xFFFFFFFFu, ps2, 2);
            if ((lane & 3) == 0) {
                atomicAdd(&rsum[rl], ps);
                atomicAdd(&rsum2[rl], ps2);
            }
        }
    }
}

__device__ __forceinline__ void ln_phase(const float* px, __half* oa,
                                         const float* rsum, const float* rsum2,
                                         const float* lng, const float* lnb,
                                         int bm, int w, int lane) {
    for (int rr = 0; rr < 16; rr++) {
        int rl = w*16 + rr;
        int m = bm + rl;
        float mu  = rsum[rl] * (1.f/CC);
        float var = rsum2[rl] * (1.f/CC) - mu*mu;
        float rst = rsqrtf(var + 1e-5f);
        #pragma unroll
        for (int i = 0; i < 3; i++) {
            int c = i*128 + lane*4;
            float4 v  = *(const float4*)(px + (size_t)m * CC + c);
            float4 gg = *(const float4*)(lng + c);
            float4 bb = *(const float4*)(lnb + c);
            *(__half2*)(oa + (size_t)m * CC + c)     = __halves2half2(
                __float2half_rn((v.x - mu)*rst*gg.x + bb.x),
                __float2half_rn((v.y - mu)*rst*gg.y + bb.y));
            *(__half2*)(oa + (size_t)m * CC + c + 2) = __halves2half2(
                __float2half_rn((v.z - mu)*rst*gg.z + bb.z),
                __float2half_rn((v.w - mu)*rst*gg.w + bb.w));
        }
    }
}

// ---------- fused embed + LN(layer0) ----------
__global__ void k_embed_ln(const int* __restrict__ idx, const float* __restrict__ tok,
                           const float* __restrict__ pos,
                           const float* __restrict__ g, const float* __restrict__ b) {
    int n = (blockIdx.x * blockDim.x + threadIdx.x) >> 5;
    int lane = threadIdx.x & 31;
    if (n >= NT) return;
    int t = n % TT;
    const float* trow = tok + (size_t)idx[n]*CC;
    const float* prow = pos + (size_t)t*CC;
    float e[12];
    float s = 0.f, s2 = 0.f;
    #pragma unroll
    for (int i = 0; i < 12; i++) {
        int c = lane + 32*i;
        e[i] = trow[c] + prow[c];
        s += e[i]; s2 += e[i]*e[i];
    }
    #pragma unroll
    for (int o = 16; o; o >>= 1) {
        s  += __shfl_xor_sync(0xFFFFFFFFu, s,  o);
        s2 += __shfl_xor_sync(0xFFFFFFFFu, s2, o);
    }
    float mu  = s  * (1.f/CC);
    float var = s2 * (1.f/CC) - mu*mu;
    float r   = rsqrtf(var + 1e-5f);
    size_t base = (size_t)n * CC;
    #pragma unroll
    for (int i = 0; i < 12; i++) {
        int c = lane + 32*i;
        g_x[base + c] = e[i];
        g_an[base + c] = __float2half_rn((e[i] - mu) * r * g[c] + b[c]);
    }
}

// ---------- weight setup ----------
__global__ void k_wsplit_qkv(const float* __restrict__ Wq, const float* __restrict__ Wk,
                             const float* __restrict__ Wv) {
    int i = blockIdx.x * blockDim.x + threadIdx.x;
    if (i >= LL*768*CC) return;
    int k = i % CC, n = (i / CC) % 768, l = i / (CC*768);
    const float* W = (n < HQ) ? Wq : (n < 2*HQ ? Wk : Wv);
    int nn = n % HQ, h = nn / HSS, d = nn % HSS;
    float v = W[(((size_t)l*HH + h)*CC + k)*HSS + d];
    g_w[(size_t)l*WSZ + W_QKV + (size_t)n*CC + k] = __float2half_rn(v);
}

#define PROJ_E (HQ*CC)
#define FF1_E  (CC*FFF)
#define LTOT   (PROJ_E + FF1_E + FF1_E)
__global__ void k_wsplit_all(const float* __restrict__ Wo, const float* __restrict__ W1,
                             const float* __restrict__ W2) {
    int i = blockIdx.x * blockDim.x + threadIdx.x;
    if (i >= LL*LTOT) return;
    int l = i / LTOT, r = i % LTOT;
    const float* W; int K, N, off;
    if (r < PROJ_E)              { W = Wo; K = HQ;  N = CC;  off = W_PROJ; }
    else if (r < PROJ_E + FF1_E) { W = W1; K = CC;  N = FFF; off = W_FF1;  r -= PROJ_E; }
    else                         { W = W2; K = FFF; N = CC;  off = W_FF2;  r -= PROJ_E + FF1_E; }
    int k = r % K, n = r / K;
    float v = W[((size_t)l*K + k)*N + n];
    g_w[(size_t)l*WSZ + off + (size_t)n*K + k] = __float2half_rn(v);
}

__global__ void k_wlmT(const float* __restrict__ Wlm) {
    int i = blockIdx.x * blockDim.x + threadIdx.x;
    if (i >= VV*CC) return;
    int v = i / CC, k = i % CC;
    g_wlmT[i] = Wlm[(size_t)k*VV + v];
}

// ---------- fp16 GEMM (QKV / FF1): C[M,N] = A[M,K] @ W[N,K]^T ----------
template<int BIAS, int RELU>
__global__ __launch_bounds__(256, 2)
void k_hgemm(const __half* __restrict__ A, const __half* __restrict__ B,
             const float* __restrict__ bias, __half* __restrict__ oh,
             int K, int N) {
    extern __shared__ char sm[];
    const uint32_t smb = s2u(sm);
    const int tid = threadIdx.x, lane = tid & 31, w = tid >> 5;
    const int wm = w & 1, wn = w >> 1;
    const int bm = blockIdx.y * 128, bn = blockIdx.x * 128;
    const int nk = K >> 6;

    float acc[4][4][4];
    #pragma unroll
    for (int i = 0; i < 4; i++)
        #pragma unroll
        for (int j = 0; j < 4; j++)
            #pragma unroll
            for (int q = 0; q < 4; q++) acc[i][j][q] = 0.f;

    load_chunk(smb, A, B, K, bm, bn, 0, tid);
    if (nk > 1) load_chunk(smb + 32768u, A, B, K, bm, bn, 64, tid);

    const int lr = lane & 15, lh = lane >> 4;
    for (int c = 0; c < nk; c++) {
        if (c + 1 < nk) { CPWAIT1(); } else { CPWAIT0(); }
        __syncthreads();
        if (c + 2 < nk)
            load_chunk(smb + (uint32_t)((c + 2) % 3) * 32768u, A, B, K, bm, bn, (c+2) << 6, tid);
        const uint32_t ab = smb + (uint32_t)(c % 3) * 32768u;
        compute_chunk(ab, ab + 16384u, acc, wm, wn, lr, lh);
    }

    const int r0 = lane >> 2, c2 = (lane & 3) * 2;
    #pragma unroll
    for (int mt = 0; mt < 4; mt++) {
        #pragma unroll
        for (int nt = 0; nt < 4; nt++) {
            int col = bn + wn*32 + nt*8 + c2;
            #pragma unroll
            for (int half = 0; half < 2; half++) {
                int m = bm + wm*64 + mt*16 + r0 + half*8;
                float v0 = acc[mt][nt][2*half], v1 = acc[mt][nt][2*half + 1];
                if (BIAS)  { v0 += bias[col]; v1 += bias[col + 1]; }
                if (RELU)  { v0 = fmaxf(v0, 0.f); v1 = fmaxf(v1, 0.f); }
                *(__half2*)(oh + (size_t)m * N + col) =
                    __halves2half2(__float2half_rn(v0), __float2half_rn(v1));
            }
        }
    }
}

// ---------- fused GEMM + residual + LayerNorm (PROJ / FF2): N = 384 ----------
__global__ __launch_bounds__(256, 2)
void k_hgemm_ln(const __half* __restrict__ A, const __half* __restrict__ B,
                const float* __restrict__ bias, float* __restrict__ px,
                __half* __restrict__ oa,
                const float* __restrict__ lng, const float* __restrict__ lnb,
                int K) {
    extern __shared__ char sm[];
    const uint32_t smb = s2u(sm);
    float* rsum  = (float*)(sm + 98304);
    float* rsum2 = rsum + 128;
    const int tid = threadIdx.x, lane = tid & 31, w = tid >> 5;
    const int wm = w & 1, wn = w >> 1;
    const int bm = blockIdx.y * 128;
    const int nkc = K >> 6;
    const int total = 3 * nkc;

    if (tid < 128) { rsum[tid] = 0.f; rsum2[tid] = 0.f; }

    float acc[4][4][4];
    #pragma unroll
    for (int i = 0; i < 4; i++)
        #pragma unroll
        for (int j = 0; j < 4; j++)
            #pragma unroll
            for (int q = 0; q < 4; q++) acc[i][j][q] = 0.f;

    load_chunk(smb, A, B, K, bm, 0, 0, tid);
    load_chunk(smb + 32768u, A, B, K, bm, 0, 64, tid);

    const int lr = lane & 15, lh = lane >> 4;
    for (int cc = 0; cc < total; cc++) {
        if (cc + 1 < total) { CPWAIT1(); } else { CPWAIT0(); }
        __syncthreads();
        if (cc + 2 < total) {
            int nc = cc + 2;
            load_chunk(smb + (uint32_t)(nc % 3) * 32768u, A, B, K,
                       bm, (nc / nkc) * 128, (nc % nkc) << 6, tid);
        }
        const uint32_t ab = smb + (uint32_t)(cc % 3) * 32768u;
        compute_chunk(ab, ab + 16384u, acc, wm, wn, lr, lh);
        if ((cc + 1) % nkc == 0)
            epi_resid(acc, bias, px, rsum, rsum2, bm, (cc / nkc) * 128, wm, wn, lane);
    }

    __syncthreads();
    ln_phase(px, oa, rsum, rsum2, lng, lnb, bm, w, lane);
}

// ---------- tensor-core flash attention, butterfly-balanced strips ----------
// Warp w processes strips w and 15-w (16 rows each): work = 5 chunks for all warps.
__global__ __launch_bounds__(256, 1)
void k_fattn() {
    extern __shared__ char sm[];
    const uint32_t smb = s2u(sm);
    const uint32_t Qb = smb, Kb = smb + 32768u, Vb = smb + 65536u;
    const int bh = blockIdx.x, bb = bh >> 2, hd = bh & 3;
    const int tid = threadIdx.x, lane = tid & 31, w = tid >> 5;

    const __half* src = g_qkvh + (size_t)(bb*TT)*768 + hd*HSS;
    #pragma unroll
    for (int i = 0; i < 8; i++) {
        int u = tid + (i << 8);
        int row = u >> 3, kc = u & 7;
        uint32_t d = (uint32_t)(row*128) + ((((uint32_t)kc) ^ (uint32_t)(row & 7)) << 4);
        const char* base = (const char*)(src + (size_t)row*768) + kc*16;
        CPA16(Qb + d, base);
        CPA16(Kb + d, base + 512);
        CPA16(Vb + d, base + 1024);
    }
    CPCOMMIT(); CPWAIT0();
    __syncthreads();

    const int lr = lane & 15, lh = lane >> 4;

    for (int si = 0; si < 2; si++) {
        const int sr = si ? (15 - w) : w;     // strip index, rows sr*16..sr*16+15
        const int rb0 = sr * 16;

        uint32_t Qf[4][4];
        {
            int row = rb0 + lr;
            uint32_t rb = Qb + (uint32_t)(row*128);
            uint32_t sel = (uint32_t)(row & 7);
            #pragma unroll
            for (int ks = 0; ks < 4; ks++)
                LDSM4(Qf[ks], rb + ((((uint32_t)(2*ks + lh)) ^ sel) << 4));
            __half2 scl = __float2half2_rn(0.125f);
            #pragma unroll
            for (int ks = 0; ks < 4; ks++)
                #pragma unroll
                for (int j = 0; j < 4; j++) {
                    __half2 v = *(__half2*)&Qf[ks][j];
                    v = __hmul2(v, scl);
                    Qf[ks][j] = *(uint32_t*)&v;
                }
        }

        float O[8][4];
        #pragma unroll
        for (int nt = 0; nt < 8; nt++)
            #pragma unroll
            for (int q = 0; q < 4; q++) O[nt][q] = 0.f;
        float mrow[2] = {-1e30f, -1e30f};
        float lrow[2] = {0.f, 0.f};

        const int dchunk = sr >> 2;           // chunk containing the diagonal
        for (int cs = 0; cs <= dchunk; cs++) {
            const bool diag = (cs == dchunk);
            float S[8][4];
            #pragma unroll
            for (int nt = 0; nt < 8; nt++)
                #pragma unroll
                for (int q = 0; q < 4; q++) S[nt][q] = 0.f;
            #pragma unroll
            for (int bt = 0; bt < 4; bt++) {
                int srow = cs*64 + bt*16 + lr;
                uint32_t rb = Kb + (uint32_t)(srow*128);
                uint32_t sel = (uint32_t)(srow & 7);
                #pragma unroll
                for (int ks = 0; ks < 4; ks++) {
                    uint32_t Kf[4];
                    LDSM4(Kf, rb + ((((uint32_t)(2*ks + lh)) ^ sel) << 4));
                    MMAH16816(S[2*bt],   Qf[ks], Kf[0], Kf[2]);
                    MMAH16816(S[2*bt+1], Qf[ks], Kf[1], Kf[3]);
                }
            }
            const int rq = rb0 + (lane >> 2);
            if (diag) {
                #pragma unroll
                for (int nt = 0; nt < 8; nt++) {
                    int col = cs*64 + nt*8 + 2*(lane & 3);
                    if (col     > rq)     S[nt][0] = -1e30f;
                    if (col + 1 > rq)     S[nt][1] = -1e30f;
                    if (col     > rq + 8) S[nt][2] = -1e30f;
                    if (col + 1 > rq + 8) S[nt][3] = -1e30f;
                }
            }
            #pragma unroll
            for (int h = 0; h < 2; h++) {
                float rmax = -1e30f;
                #pragma unroll
                for (int nt = 0; nt < 8; nt++)
                    rmax = fmaxf(rmax, fmaxf(S[nt][2*h], S[nt][2*h+1]));
                rmax = fmaxf(rmax, __shfl_xor_sync(0xFFFFFFFFu, rmax, 1));
                rmax = fmaxf(rmax, __shfl_xor_sync(0xFFFFFFFFu, rmax, 2));
                float mn = fmaxf(mrow[h], rmax);
                float corr = __expf(mrow[h] - mn);
                mrow[h] = mn;
                float rsumv = 0.f;
                #pragma unroll
                for (int nt = 0; nt < 8; nt++) {
                    float e0 = __expf(S[nt][2*h]   - mn);
                    float e1 = __expf(S[nt][2*h+1] - mn);
                    S[nt][2*h] = e0; S[nt][2*h+1] = e1;
                    rsumv += e0 + e1;
                }
                rsumv += __shfl_xor_sync(0xFFFFFFFFu, rsumv, 1);
                rsumv += __shfl_xor_sync(0xFFFFFFFFu, rsumv, 2);
                lrow[h] = lrow[h]*corr + rsumv;
                #pragma unroll
                for (int nt = 0; nt < 8; nt++) {
                    O[nt][2*h]   *= corr;
                    O[nt][2*h+1] *= corr;
                }
            }
            #pragma unroll
            for (int ks = 0; ks < 4; ks++) {
                uint32_t Pf[4];
                Pf[0] = packh2(S[2*ks][0],   S[2*ks][1]);
                Pf[1] = packh2(S[2*ks][2],   S[2*ks][3]);
                Pf[2] = packh2(S[2*ks+1][0], S[2*ks+1][1]);
                Pf[3] = packh2(S[2*ks+1][2], S[2*ks+1][3]);
                int srow = cs*64 + ks*16 + lr;
                uint32_t rb = Vb + (uint32_t)(srow*128);
                uint32_t sel = (uint32_t)(srow & 7);
                #pragma unroll
                for (int dv = 0; dv < 4; dv++) {
                    uint32_t Vf[4];
                    LDSMT4(Vf, rb + ((((uint32_t)(2*dv + lh)) ^ sel) << 4));
                    MMAH16816(O[2*dv],   Pf, Vf[0], Vf[1]);
                    MMAH16816(O[2*dv+1], Pf, Vf[2], Vf[3]);
                }
            }
        }

        float inv0 = 1.f / lrow[0];
        float inv1 = 1.f / lrow[1];
        int r0 = rb0 + (lane >> 2);
        __half* d0 = g_a + (size_t)(bb*TT + r0)*HQ + hd*HSS + 2*(lane & 3);
        __half* d1 = d0 + 8*HQ;
        #pragma unroll
        for (int nt = 0; nt < 8; nt++) {
            *(__half2*)(d0 + nt*8) = __halves2half2(
                __float2half_rn(O[nt][0]*inv0), __float2half_rn(O[nt][1]*inv0));
            *(__half2*)(d1 + nt*8) = __halves2half2(
                __float2half_rn(O[nt][2]*inv1), __float2half_rn(O[nt][3]*inv1));
        }
    }
}

// ---------- fused LM head + NLL (reads fp16 g_an) ----------
__global__ __launch_bounds__(128)
void k_lmhead(const float* __restrict__ blm, float* __restrict__ out,
              const int* __restrict__ tgt) {
    __shared__ float a[CC];
    __shared__ float lg[VV];
    int n = blockIdx.x;
    const __half* row = g_an + (size_t)n * CC;
    for (int c = threadIdx.x; c < CC; c += 128) a[c] = __half2float(row[c]);
    __syncthreads();
    int v = threadIdx.x;
    if (v < VV) {
        float s = blm[v];
        const float4* w4 = (const float4*)(g_wlmT + (size_t)v * CC);
        const float4* a4 = (const float4*)a;
        #pragma unroll 8
        for (int k = 0; k < CC/4; k++) {
            float4 w = w4[k], x = a4[k];
            s += x.x*w.x + x.y*w.y + x.z*w.z + x.w*w.w;
        }
        lg[v] = s;
        out[(size_t)n * VV + v] = s;
    }
    __syncthreads();
    if (threadIdx.x < 32) {
        int lane = threadIdx.x;
        float m1 = (lane      < VV) ? lg[lane]      : -1e30f;
        float m2 = (lane + 32 < VV) ? lg[lane + 32] : -1e30f;
        float m3 = (lane + 64 < VV) ? lg[lane + 64] : -1e30f;
        float mxv = fmaxf(m1, fmaxf(m2, m3));
        #pragma unroll
        for (int o = 16; o; o >>= 1) mxv = fmaxf(mxv, __shfl_xor_sync(0xFFFFFFFFu, mxv, o));
        float s = ((lane      < VV) ? expf(lg[lane]      - mxv) : 0.f)
                + ((lane + 32 < VV) ? expf(lg[lane + 32] - mxv) : 0.f)
                + ((lane + 64 < VV) ? expf(lg[lane + 64] - mxv) : 0.f);
        #pragma unroll
        for (int o = 16; o; o >>= 1) s += __shfl_xor_sync(0xFFFFFFFFu, s, o);
        if (lane == 0) g_nll[n] = logf(s) + mxv - lg[tgt[n]];
    }
}

__global__ void k_loss(float* __restrict__ out, int write_idx) {
    __shared__ float sh[256];
    float s = 0.f;
    for (int i = threadIdx.x; i < NT; i += 256) s += g_nll[i];
    sh[threadIdx.x] = s;
    __syncthreads();
    for (int o = 128; o; o >>= 1) {
        if (threadIdx.x < o) sh[threadIdx.x] += sh[threadIdx.x + o];
        __syncthreads();
    }
    if (threadIdx.x == 0) out[write_idx] = sh[0] / (float)NT;
}

// ---------- launch ----------
extern "C" void kernel_launch(void* const* d_in, const int* in_sizes, int n_in,
                              void* d_out, int out_size) {
    const int*   idx  = (const int*)  d_in[0];
    const int*   tgt  = (const int*)  d_in[1];
    const float* tok  = (const float*)d_in[2];
    const float* pos  = (const float*)d_in[3];
    const float* Wq   = (const float*)d_in[4];
    const float* Wk   = (const float*)d_in[5];
    const float* Wv   = (const float*)d_in[6];
    const float* Wo   = (const float*)d_in[7];
    const float* bo   = (const float*)d_in[8];
    const float* W1   = (const float*)d_in[9];
    const float* b1   = (const float*)d_in[10];
    const float* W2   = (const float*)d_in[11];
    const float* b2   = (const float*)d_in[12];
    const float* ln1g = (const float*)d_in[13];
    const float* ln1b = (const float*)d_in[14];
    const float* ln2g = (const float*)d_in[15];
    const float* ln2b = (const float*)d_in[16];
    const float* lnfg = (const float*)d_in[17];
    const float* lnfb = (const float*)d_in[18];
    const float* Wlm  = (const float*)d_in[19];
    const float* blm  = (const float*)d_in[20];
    float* out = (float*)d_out;

    float *px;
    __half *pa, *pan, *ph, *pw, *pqkvh;
    cudaGetSymbolAddress((void**)&px,    g_x);
    cudaGetSymbolAddress((void**)&pa,    g_a);
    cudaGetSymbolAddress((void**)&pan,   g_an);
    cudaGetSymbolAddress((void**)&ph,    g_h);
    cudaGetSymbolAddress((void**)&pqkvh, g_qkvh);
    cudaGetSymbolAddress((void**)&pw,    g_w);

    const int SMEM  = 3 * 32768;
    const int SMEML = 3 * 32768 + 1024;
    cudaFuncSetAttribute(k_hgemm<0,0>, cudaFuncAttributeMaxDynamicSharedMemorySize, SMEM);
    cudaFuncSetAttribute(k_hgemm<1,1>, cudaFuncAttributeMaxDynamicSharedMemorySize, SMEM);
    cudaFuncSetAttribute(k_hgemm_ln,   cudaFuncAttributeMaxDynamicSharedMemorySize, SMEML);
    cudaFuncSetAttribute(k_fattn,      cudaFuncAttributeMaxDynamicSharedMemorySize, SMEM);

    // launch order: index 3 = QKV GEMM, index 4 = fattn (ncu window)
    k_embed_ln<<<NT/8, 256>>>(idx, tok, pos, ln1g, ln1b);                     // 0
    k_wsplit_qkv<<<(LL*768*CC + 255)/256, 256>>>(Wq, Wk, Wv);                 // 1
    k_wsplit_all<<<(LL*LTOT + 255)/256, 256>>>(Wo, W1, W2);                   // 2
    k_hgemm<0,0><<<dim3(6, NT/128), 256, SMEM>>>(                             // 3
        pan, pw + W_QKV, nullptr, pqkvh, CC, 3*HQ);
    k_fattn<<<BB*HH, 256, SMEM>>>();                                          // 4
    k_wlmT<<<(VV*CC + 255)/256, 256>>>(Wlm);                                  // 5

    for (int l = 0; l < LL; l++) {
        const __half* wl = pw + (size_t)l*WSZ;
        if (l > 0) {
            k_hgemm<0,0><<<dim3(6, NT/128), 256, SMEM>>>(
                pan, wl + W_QKV, nullptr, pqkvh, CC, 3*HQ);
            k_fattn<<<BB*HH, 256, SMEM>>>();
        }
        // PROJ + residual + LN2 (fused)
        k_hgemm_ln<<<dim3(1, NT/128), 256, SMEML>>>(
            pa, wl + W_PROJ, bo + l*CC, px, pan, ln2g + l*CC, ln2b + l*CC, HQ);
        // FF1 + bias + relu
        k_hgemm<1,1><<<dim3(12, NT/128), 256, SMEM>>>(
            pan, wl + W_FF1, b1 + l*FFF, ph, CC, FFF);
        // FF2 + residual + LN (next layer's LN1, or final LN)
        const float* ng = (l + 1 < LL) ? ln1g + (l+1)*CC : lnfg;
        const float* nb = (l + 1 < LL) ? ln1b + (l+1)*CC : lnfb;
        k_hgemm_ln<<<dim3(1, NT/128), 256, SMEML>>>(
            ph, wl + W_FF2, b2 + l*CC, px, pan, ng, nb, FFF);
    }

    k_lmhead<<<NT, 128>>>(blm, out, tgt);
    if (out_size == 1)         k_loss<<<1, 256>>>(out, 0);
    else if (out_size > NT*VV) k_loss<<<1, 256>>>(out, NT*VV);
}

// round 16
// speedup vs baseline: 1.2387x; 1.2387x over previous
#include <cuda_runtime.h>
#include <cuda_fp16.h>
#include <cstdint>
#include <math.h>

#define BB 128
#define TT 256
#define CC 384
#define HH 4
#define HSS 64
#define LL 6
#define VV 65
#define FFF 1536
#define NT (BB*TT)
#define HQ (HH*HSS)

#define WSZ 1572864
#define W_QKV 0
#define W_PROJ 294912
#define W_FF1 393216
#define W_FF2 983040

__device__ float g_x[NT*CC];          // fp32 residual
__device__ __half g_qkvh[NT*3*HQ];    // q|k|v fp16
__device__ __half g_a[NT*HQ];         // attention output (stride HQ)
__device__ __half g_an[NT*CC];        // LN output (stride CC) - GEMM A operand
__device__ __half g_h[NT*FFF];        // FF hidden
__device__ __half g_w[LL*WSZ];        // fp16 weights [l][n][k]
__device__ __half g_wlmh[128*CC];     // LM head fp16 [128 padded rows][384]
__device__ float g_nll[NT];

// ---------- PTX helpers ----------
__device__ __forceinline__ uint32_t s2u(const void* p) {
    uint32_t a;
    asm("{ .reg .u64 t; cvta.to.shared.u64 t, %1; cvt.u32.u64 %0, t; }" : "=r"(a) : "l"(p));
    return a;
}
#define CPA16(d,s) asm volatile("cp.async.cg.shared.global [%0], [%1], 16;" :: "r"(d), "l"(s))
#define CPCOMMIT() asm volatile("cp.async.commit_group;" ::: "memory")
#define CPWAIT0()  asm volatile("cp.async.wait_group 0;" ::: "memory")
#define CPWAIT1()  asm volatile("cp.async.wait_group 1;" ::: "memory")

#define LDSM4(r, a) \
    asm volatile("ldmatrix.sync.aligned.m8n8.x4.shared.b16 {%0,%1,%2,%3}, [%4];" \
        : "=r"((r)[0]), "=r"((r)[1]), "=r"((r)[2]), "=r"((r)[3]) : "r"(a))

#define LDSMT4(r, a) \
    asm volatile("ldmatrix.sync.aligned.m8n8.x4.trans.shared.b16 {%0,%1,%2,%3}, [%4];" \
        : "=r"((r)[0]), "=r"((r)[1]), "=r"((r)[2]), "=r"((r)[3]) : "r"(a))

#define MMAH16816(d, a, b0, b1) \
    asm volatile("mma.sync.aligned.m16n8k16.row.col.f32.f16.f16.f32 " \
        "{%0,%1,%2,%3}, {%4,%5,%6,%7}, {%8,%9}, {%0,%1,%2,%3};" \
        : "+f"((d)[0]), "+f"((d)[1]), "+f"((d)[2]), "+f"((d)[3]) \
        : "r"((a)[0]), "r"((a)[1]), "r"((a)[2]), "r"((a)[3]), "r"(b0), "r"(b1))

__device__ __forceinline__ uint32_t packh2(float a, float b) {
    __half2 h = __halves2half2(__float2half_rn(a), __float2half_rn(b));
    return *(uint32_t*)&h;
}

// ---------- shared GEMM building blocks ----------
__device__ __forceinline__ void load_chunk(uint32_t base, const __half* A, const __half* B,
                                           int K, int bm, int bn, int k0, int tid) {
    #pragma unroll
    for (int i = 0; i < 4; i++) {
        int u = tid + (i << 8);
        int row = u >> 3, kc = u & 7;
        uint32_t d = (uint32_t)(row*128) + ((((uint32_t)kc) ^ (uint32_t)(row & 7)) << 4);
        CPA16(base + d,          (const char*)(A + (size_t)(bm + row) * K + k0) + kc*16);
        CPA16(base + 16384u + d, (const char*)(B + (size_t)(bn + row) * K + k0) + kc*16);
    }
    CPCOMMIT();
}

__device__ __forceinline__ void compute_chunk(uint32_t ab, uint32_t bb,
                                              float (&acc)[4][4][4],
                                              int wm, int wn, int lr, int lh) {
    #pragma unroll
    for (int s = 0; s < 4; s++) {
        uint32_t Bf[2][4];
        #pragma unroll
        for (int bt = 0; bt < 2; bt++) {
            int row = wn*32 + bt*16 + lr;
            uint32_t d = (uint32_t)(row*128) +
                ((((uint32_t)(2*s + lh)) ^ (uint32_t)(row & 7)) << 4);
            LDSM4(Bf[bt], bb + d);
        }
        uint32_t Af[2][4];
        {
            int row = wm*64 + lr;
            uint32_t d = (uint32_t)(row*128) +
                ((((uint32_t)(2*s + lh)) ^ (uint32_t)(row & 7)) << 4);
            LDSM4(Af[0], ab + d);
        }
        #pragma unroll
        for (int mt = 0; mt < 4; mt++) {
            if (mt < 3) {
                int row = wm*64 + (mt+1)*16 + lr;
                uint32_t d = (uint32_t)(row*128) +
                    ((((uint32_t)(2*s + lh)) ^ (uint32_t)(row & 7)) << 4);
                LDSM4(Af[(mt+1) & 1], ab + d);
            }
            const uint32_t* Ac = Af[mt & 1];
            #pragma unroll
            for (int nt = 0; nt < 4; nt++) {
                int g = nt >> 1, j = nt & 1;
                MMAH16816(acc[mt][nt], Ac, Bf[g][j], Bf[g][j+2]);
            }
        }
    }
}

__device__ __forceinline__ void epi_resid(float (&acc)[4][4][4], const float* bias,
                                          float* px, float* rsum, float* rsum2,
                                          int bm, int bn, int wm, int wn, int lane) {
    const int r0 = lane >> 2, c2 = (lane & 3) * 2;
    #pragma unroll
    for (int mt = 0; mt < 4; mt++) {
        #pragma unroll
        for (int half = 0; half < 2; half++) {
            int rl = wm*64 + mt*16 + r0 + half*8;
            int m = bm + rl;
            float ps = 0.f, ps2 = 0.f;
            #pragma unroll
            for (int nt = 0; nt < 4; nt++) {
                int col = bn + wn*32 + nt*8 + c2;
                float v0 = acc[mt][nt][2*half]   + bias[col];
                float v1 = acc[mt][nt][2*half+1] + bias[col+1];
                float2 t = *(const float2*)(px + (size_t)m * CC + col);
                v0 += t.x; v1 += t.y;
                *(float2*)(px + (size_t)m * CC + col) = make_float2(v0, v1);
                ps  += v0 + v1;
                ps2 += v0*v0 + v1*v1;
                acc[mt][nt][2*half] = 0.f;
                acc[mt][nt][2*half+1] = 0.f;
            }
            ps  += __shfl_xor_sync(0xFFFFFFFFu, ps,  1);
            ps  += __shfl_xor_sync(0xFFFFFFFFu, ps,  2);
            ps2 += __shfl_xor_sync(0xFFFFFFFFu, ps2, 1);
            ps2 += __shfl_xor_sync(0xFFFFFFFFu, ps2, 2);
            if ((lane & 3) == 0) {
                atomicAdd(&rsum[rl], ps);
                atomicAdd(&rsum2[rl], ps2);
            }
        }
    }
}

__device__ __forceinline__ void ln_phase(const float* px, __half* oa,
                                         const float* rsum, const float* rsum2,
                                         const float* lng, const float* lnb,
                                         int bm, int w, int lane) {
    for (int rr = 0; rr < 16; rr++) {
        int rl = w*16 + rr;
        int m = bm + rl;
        float mu  = rsum[rl] * (1.f/CC);
        float var = rsum2[rl] * (1.f/CC) - mu*mu;
        float rst = rsqrtf(var + 1e-5f);
        #pragma unroll
        for (int i = 0; i < 3; i++) {
            int c = i*128 + lane*4;
            float4 v  = *(const float4*)(px + (size_t)m * CC + c);
            float4 gg = *(const float4*)(lng + c);
            float4 bb = *(const float4*)(lnb + c);
            *(__half2*)(oa + (size_t)m * CC + c)     = __halves2half2(
                __float2half_rn((v.x - mu)*rst*gg.x + bb.x),
                __float2half_rn((v.y - mu)*rst*gg.y + bb.y));
            *(__half2*)(oa + (size_t)m * CC + c + 2) = __halves2half2(
                __float2half_rn((v.z - mu)*rst*gg.z + bb.z),
                __float2half_rn((v.w - mu)*rst*gg.w + bb.w));
        }
    }
}

// ---------- fused embed + LN(layer0) ----------
__global__ void k_embed_ln(const int* __restrict__ idx, const float* __restrict__ tok,
                           const float* __restrict__ pos,
                           const float* __restrict__ g, const float* __restrict__ b) {
    int n = (blockIdx.x * blockDim.x + threadIdx.x) >> 5;
    int lane = threadIdx.x & 31;
    if (n >= NT) return;
    int t = n % TT;
    const float* trow = tok + (size_t)idx[n]*CC;
    const float* prow = pos + (size_t)t*CC;
    float e[12];
    float s = 0.f, s2 = 0.f;
    #pragma unroll
    for (int i = 0; i < 12; i++) {
        int c = lane + 32*i;
        e[i] = trow[c] + prow[c];
        s += e[i]; s2 += e[i]*e[i];
    }
    #pragma unroll
    for (int o = 16; o; o >>= 1) {
        s  += __shfl_xor_sync(0xFFFFFFFFu, s,  o);
        s2 += __shfl_xor_sync(0xFFFFFFFFu, s2, o);
    }
    float mu  = s  * (1.f/CC);
    float var = s2 * (1.f/CC) - mu*mu;
    float r   = rsqrtf(var + 1e-5f);
    size_t base = (size_t)n * CC;
    #pragma unroll
    for (int i = 0; i < 12; i++) {
        int c = lane + 32*i;
        g_x[base + c] = e[i];
        g_an[base + c] = __float2half_rn((e[i] - mu) * r * g[c] + b[c]);
    }
}

// ---------- weight setup ----------
__global__ void k_wsplit_qkv(const float* __restrict__ Wq, const float* __restrict__ Wk,
                             const float* __restrict__ Wv) {
    int i = blockIdx.x * blockDim.x + threadIdx.x;
    if (i >= LL*768*CC) return;
    int k = i % CC, n = (i / CC) % 768, l = i / (CC*768);
    const float* W = (n < HQ) ? Wq : (n < 2*HQ ? Wk : Wv);
    int nn = n % HQ, h = nn / HSS, d = nn % HSS;
    float v = W[(((size_t)l*HH + h)*CC + k)*HSS + d];
    g_w[(size_t)l*WSZ + W_QKV + (size_t)n*CC + k] = __float2half_rn(v);
}

#define PROJ_E (HQ*CC)
#define FF1_E  (CC*FFF)
#define LTOT   (PROJ_E + FF1_E + FF1_E)
__global__ void k_wsplit_all(const float* __restrict__ Wo, const float* __restrict__ W1,
                             const float* __restrict__ W2) {
    int i = blockIdx.x * blockDim.x + threadIdx.x;
    if (i >= LL*LTOT) return;
    int l = i / LTOT, r = i % LTOT;
    const float* W; int K, N, off;
    if (r < PROJ_E)              { W = Wo; K = HQ;  N = CC;  off = W_PROJ; }
    else if (r < PROJ_E + FF1_E) { W = W1; K = CC;  N = FFF; off = W_FF1;  r -= PROJ_E; }
    else                         { W = W2; K = FFF; N = CC;  off = W_FF2;  r -= PROJ_E + FF1_E; }
    int k = r % K, n = r / K;
    float v = W[((size_t)l*K + k)*N + n];
    g_w[(size_t)l*WSZ + off + (size_t)n*K + k] = __float2half_rn(v);
}

// LM head: fp16, [128 padded rows][384], rows >= VV are zero
__global__ void k_wlmh(const float* __restrict__ Wlm) {
    int i = blockIdx.x * blockDim.x + threadIdx.x;
    if (i >= 128*CC) return;
    int v = i / CC, k = i % CC;
    g_wlmh[i] = (v < VV) ? __float2half_rn(Wlm[(size_t)k*VV + v]) : __float2half_rn(0.f);
}

// ---------- fp16 GEMM (QKV / FF1): C[M,N] = A[M,K] @ W[N,K]^T ----------
template<int BIAS, int RELU>
__global__ __launch_bounds__(256, 2)
void k_hgemm(const __half* __restrict__ A, const __half* __restrict__ B,
             const float* __restrict__ bias, __half* __restrict__ oh,
             int K, int N) {
    extern __shared__ char sm[];
    const uint32_t smb = s2u(sm);
    const int tid = threadIdx.x, lane = tid & 31, w = tid >> 5;
    const int wm = w & 1, wn = w >> 1;
    const int bm = blockIdx.y * 128, bn = blockIdx.x * 128;
    const int nk = K >> 6;

    float acc[4][4][4];
    #pragma unroll
    for (int i = 0; i < 4; i++)
        #pragma unroll
        for (int j = 0; j < 4; j++)
            #pragma unroll
            for (int q = 0; q < 4; q++) acc[i][j][q] = 0.f;

    load_chunk(smb, A, B, K, bm, bn, 0, tid);
    if (nk > 1) load_chunk(smb + 32768u, A, B, K, bm, bn, 64, tid);

    const int lr = lane & 15, lh = lane >> 4;
    for (int c = 0; c < nk; c++) {
        if (c + 1 < nk) { CPWAIT1(); } else { CPWAIT0(); }
        __syncthreads();
        if (c + 2 < nk)
            load_chunk(smb + (uint32_t)((c + 2) % 3) * 32768u, A, B, K, bm, bn, (c+2) << 6, tid);
        const uint32_t ab = smb + (uint32_t)(c % 3) * 32768u;
        compute_chunk(ab, ab + 16384u, acc, wm, wn, lr, lh);
    }

    const int r0 = lane >> 2, c2 = (lane & 3) * 2;
    #pragma unroll
    for (int mt = 0; mt < 4; mt++) {
        #pragma unroll
        for (int nt = 0; nt < 4; nt++) {
            int col = bn + wn*32 + nt*8 + c2;
            #pragma unroll
            for (int half = 0; half < 2; half++) {
                int m = bm + wm*64 + mt*16 + r0 + half*8;
                float v0 = acc[mt][nt][2*half], v1 = acc[mt][nt][2*half + 1];
                if (BIAS)  { v0 += bias[col]; v1 += bias[col + 1]; }
                if (RELU)  { v0 = fmaxf(v0, 0.f); v1 = fmaxf(v1, 0.f); }
                *(__half2*)(oh + (size_t)m * N + col) =
                    __halves2half2(__float2half_rn(v0), __float2half_rn(v1));
            }
        }
    }
}

// ---------- LM-head GEMM: logits[M,65] = A[M,384] @ Wlm[128,384]^T (guarded) ----
__global__ __launch_bounds__(256, 2)
void k_hgemm_lm(const __half* __restrict__ A, const float* __restrict__ blm,
                float* __restrict__ out) {
    extern __shared__ char sm[];
    const uint32_t smb = s2u(sm);
    const int tid = threadIdx.x, lane = tid & 31, w = tid >> 5;
    const int wm = w & 1, wn = w >> 1;
    const int bm = blockIdx.y * 128;
    const int nk = CC >> 6;   // 6

    float acc[4][4][4];
    #pragma unroll
    for (int i = 0; i < 4; i++)
        #pragma unroll
        for (int j = 0; j < 4; j++)
            #pragma unroll
            for (int q = 0; q < 4; q++) acc[i][j][q] = 0.f;

    load_chunk(smb, A, g_wlmh, CC, bm, 0, 0, tid);
    load_chunk(smb + 32768u, A, g_wlmh, CC, bm, 0, 64, tid);

    const int lr = lane & 15, lh = lane >> 4;
    for (int c = 0; c < nk; c++) {
        if (c + 1 < nk) { CPWAIT1(); } else { CPWAIT0(); }
        __syncthreads();
        if (c + 2 < nk)
            load_chunk(smb + (uint32_t)((c + 2) % 3) * 32768u, A, g_wlmh, CC,
                       bm, 0, (c+2) << 6, tid);
        const uint32_t ab = smb + (uint32_t)(c % 3) * 32768u;
        compute_chunk(ab, ab + 16384u, acc, wm, wn, lr, lh);
    }

    const int r0 = lane >> 2, c2 = (lane & 3) * 2;
    #pragma unroll
    for (int mt = 0; mt < 4; mt++) {
        #pragma unroll
        for (int nt = 0; nt < 4; nt++) {
            int col = wn*32 + nt*8 + c2;
            if (col >= VV) continue;
            #pragma unroll
            for (int half = 0; half < 2; half++) {
                int m = bm + wm*64 + mt*16 + r0 + half*8;
                float v0 = acc[mt][nt][2*half]     + blm[col];
                out[(size_t)m * VV + col] = v0;
                if (col + 1 < VV) {
                    float v1 = acc[mt][nt][2*half+1] + blm[col+1];
                    out[(size_t)m * VV + col + 1] = v1;
                }
            }
        }
    }
}

// ---------- fused GEMM + residual + LayerNorm (PROJ / FF2): N = 384 ----------
__global__ __launch_bounds__(256, 2)
void k_hgemm_ln(const __half* __restrict__ A, const __half* __restrict__ B,
                const float* __restrict__ bias, float* __restrict__ px,
                __half* __restrict__ oa,
                const float* __restrict__ lng, const float* __restrict__ lnb,
                int K) {
    extern __shared__ char sm[];
    const uint32_t smb = s2u(sm);
    float* rsum  = (float*)(sm + 98304);
    float* rsum2 = rsum + 128;
    const int tid = threadIdx.x, lane = tid & 31, w = tid >> 5;
    const int wm = w & 1, wn = w >> 1;
    const int bm = blockIdx.y * 128;
    const int nkc = K >> 6;
    const int total = 3 * nkc;

    if (tid < 128) { rsum[tid] = 0.f; rsum2[tid] = 0.f; }

    float acc[4][4][4];
    #pragma unroll
    for (int i = 0; i < 4; i++)
        #pragma unroll
        for (int j = 0; j < 4; j++)
            #pragma unroll
            for (int q = 0; q < 4; q++) acc[i][j][q] = 0.f;

    load_chunk(smb, A, B, K, bm, 0, 0, tid);
    load_chunk(smb + 32768u, A, B, K, bm, 0, 64, tid);

    const int lr = lane & 15, lh = lane >> 4;
    for (int cc = 0; cc < total; cc++) {
        if (cc + 1 < total) { CPWAIT1(); } else { CPWAIT0(); }
        __syncthreads();
        if (cc + 2 < total) {
            int nc = cc + 2;
            load_chunk(smb + (uint32_t)(nc % 3) * 32768u, A, B, K,
                       bm, (nc / nkc) * 128, (nc % nkc) << 6, tid);
        }
        const uint32_t ab = smb + (uint32_t)(cc % 3) * 32768u;
        compute_chunk(ab, ab + 16384u, acc, wm, wn, lr, lh);
        if ((cc + 1) % nkc == 0)
            epi_resid(acc, bias, px, rsum, rsum2, bm, (cc / nkc) * 128, wm, wn, lane);
    }

    __syncthreads();
    ln_phase(px, oa, rsum, rsum2, lng, lnb, bm, w, lane);
}

// ---------- tensor-core flash attention (two-chain, R13 form) ----------
__global__ __launch_bounds__(256, 1)
void k_fattn() {
    extern __shared__ char sm[];
    const uint32_t smb = s2u(sm);
    const uint32_t Qb = smb, Kb = smb + 32768u, Vb = smb + 65536u;
    const int bh = blockIdx.x, bb = bh >> 2, hd = bh & 3;
    const int tid = threadIdx.x, lane = tid & 31, w = tid >> 5;

    const __half* src = g_qkvh + (size_t)(bb*TT)*768 + hd*HSS;
    #pragma unroll
    for (int i = 0; i < 8; i++) {
        int u = tid + (i << 8);
        int row = u >> 3, kc = u & 7;
        uint32_t d = (uint32_t)(row*128) + ((((uint32_t)kc) ^ (uint32_t)(row & 7)) << 4);
        const char* base = (const char*)(src + (size_t)row*768) + kc*16;
        CPA16(Qb + d, base);
        CPA16(Kb + d, base + 512);
        CPA16(Vb + d, base + 1024);
    }
    CPCOMMIT(); CPWAIT0();
    __syncthreads();

    const int lr = lane & 15, lh = lane >> 4;

    uint32_t Qf[2][4][4];
    #pragma unroll
    for (int mt = 0; mt < 2; mt++) {
        int row = w*32 + mt*16 + lr;
        uint32_t rb = Qb + (uint32_t)(row*128);
        uint32_t sel = (uint32_t)(row & 7);
        #pragma unroll
        for (int ks = 0; ks < 4; ks++)
            LDSM4(Qf[mt][ks], rb + ((((uint32_t)(2*ks + lh)) ^ sel) << 4));
    }
    {
        __half2 scl = __float2half2_rn(0.125f);
        #pragma unroll
        for (int mt = 0; mt < 2; mt++)
            #pragma unroll
            for (int ks = 0; ks < 4; ks++)
                #pragma unroll
                for (int j = 0; j < 4; j++) {
                    __half2 v = *(__half2*)&Qf[mt][ks][j];
                    v = __hmul2(v, scl);
                    Qf[mt][ks][j] = *(uint32_t*)&v;
                }
    }

    float O[2][8][4];
    #pragma unroll
    for (int mt = 0; mt < 2; mt++)
        #pragma unroll
        for (int nt = 0; nt < 8; nt++)
            #pragma unroll
            for (int q = 0; q < 4; q++) O[mt][nt][q] = 0.f;
    float mrow[2][2] = {{-1e30f,-1e30f},{-1e30f,-1e30f}};
    float lrow[2][2] = {{0.f,0.f},{0.f,0.f}};

    const int nch = (w >> 1) + 1;
    for (int cs = 0; cs < nch; cs++) {
        const bool diag = (cs == (w >> 1));
        #pragma unroll
        for (int mt = 0; mt < 2; mt++) {
            float S[8][4];
            #pragma unroll
            for (int nt = 0; nt < 8; nt++)
                #pragma unroll
                for (int q = 0; q < 4; q++) S[nt][q] = 0.f;
            #pragma unroll
            for (int bt = 0; bt < 4; bt++) {
                int srow = cs*64 + bt*16 + lr;
                uint32_t rb = Kb + (uint32_t)(srow*128);
                uint32_t sel = (uint32_t)(srow & 7);
                #pragma unroll
                for (int ks = 0; ks < 4; ks++) {
                    uint32_t Kf[4];
                    LDSM4(Kf, rb + ((((uint32_t)(2*ks + lh)) ^ sel) << 4));
                    MMAH16816(S[2*bt],   Qf[mt][ks], Kf[0], Kf[2]);
                    MMAH16816(S[2*bt+1], Qf[mt][ks], Kf[1], Kf[3]);
                }
            }
            const int rbase = w*32 + mt*16 + (lane >> 2);
            if (diag) {
                #pragma unroll
                for (int nt = 0; nt < 8; nt++) {
                    int col = cs*64 + nt*8 + 2*(lane & 3);
                    if (col     > rbase)     S[nt][0] = -1e30f;
                    if (col + 1 > rbase)     S[nt][1] = -1e30f;
                    if (col     > rbase + 8) S[nt][2] = -1e30f;
                    if (col + 1 > rbase + 8) S[nt][3] = -1e30f;
                }
            }
            #pragma unroll
            for (int h = 0; h < 2; h++) {
                float rmax = -1e30f;
                #pragma unroll
                for (int nt = 0; nt < 8; nt++)
                    rmax = fmaxf(rmax, fmaxf(S[nt][2*h], S[nt][2*h+1]));
                rmax = fmaxf(rmax, __shfl_xor_sync(0xFFFFFFFFu, rmax, 1));
                rmax = fmaxf(rmax, __shfl_xor_sync(0xFFFFFFFFu, rmax, 2));
                float mn = fmaxf(mrow[mt][h], rmax);
                float corr = __expf(mrow[mt][h] - mn);
                mrow[mt][h] = mn;
                float rsumv = 0.f;
                #pragma unroll
                for (int nt = 0; nt < 8; nt++) {
                    float e0 = __expf(S[nt][2*h]   - mn);
                    float e1 = __expf(S[nt][2*h+1] - mn);
                    S[nt][2*h] = e0; S[nt][2*h+1] = e1;
                    rsumv += e0 + e1;
                }
                rsumv += __shfl_xor_sync(0xFFFFFFFFu, rsumv, 1);
                rsumv += __shfl_xor_sync(0xFFFFFFFFu, rsumv, 2);
                lrow[mt][h] = lrow[mt][h]*corr + rsumv;
                #pragma unroll
                for (int nt = 0; nt < 8; nt++) {
                    O[mt][nt][2*h]   *= corr;
                    O[mt][nt][2*h+1] *= corr;
                }
            }
            #pragma unroll
            for (int ks = 0; ks < 4; ks++) {
                uint32_t Pf[4];
                Pf[0] = packh2(S[2*ks][0],   S[2*ks][1]);
                Pf[1] = packh2(S[2*ks][2],   S[2*ks][3]);
                Pf[2] = packh2(S[2*ks+1][0], S[2*ks+1][1]);
                Pf[3] = packh2(S[2*ks+1][2], S[2*ks+1][3]);
                int srow = cs*64 + ks*16 + lr;
                uint32_t rb = Vb + (uint32_t)(srow*128);
                uint32_t sel = (uint32_t)(srow & 7);
                #pragma unroll
                for (int dv = 0; dv < 4; dv++) {
                    uint32_t Vf[4];
                    LDSMT4(Vf, rb + ((((uint32_t)(2*dv + lh)) ^ sel) << 4));
                    MMAH16816(O[mt][2*dv],   Pf, Vf[0], Vf[1]);
                    MMAH16816(O[mt][2*dv+1], Pf, Vf[2], Vf[3]);
                }
            }
        }
    }
    #pragma unroll
    for (int mt = 0; mt < 2; mt++) {
        float inv0 = 1.f / lrow[mt][0];
        float inv1 = 1.f / lrow[mt][1];
        int r0 = w*32 + mt*16 + (lane >> 2);
        __half* d0 = g_a + (size_t)(bb*TT + r0)*HQ + hd*HSS + 2*(lane & 3);
        __half* d1 = d0 + 8*HQ;
        #pragma unroll
        for (int nt = 0; nt < 8; nt++) {
            *(__half2*)(d0 + nt*8) = __halves2half2(
                __float2half_rn(O[mt][nt][0]*inv0), __float2half_rn(O[mt][nt][1]*inv0));
            *(__half2*)(d1 + nt*8) = __halves2half2(
                __float2half_rn(O[mt][nt][2]*inv1), __float2half_rn(O[mt][nt][3]*inv1));
        }
    }
}

// ---------- NLL: warp per row over VV logits ----------
__global__ void k_nll(const float* __restrict__ logits, const int* __restrict__ tgt) {
    int warp = (blockIdx.x * blockDim.x + threadIdx.x) >> 5;
    int lane = threadIdx.x & 31;
    if (warp >= NT) return;
    const float* row = logits + (size_t)warp * VV;
    float mx = -1e30f;
    for (int v = lane; v < VV; v += 32) mx = fmaxf(mx, row[v]);
    #pragma unroll
    for (int o = 16; o; o >>= 1) mx = fmaxf(mx, __shfl_xor_sync(0xFFFFFFFFu, mx, o));
    float s = 0.f;
    for (int v = lane; v < VV; v += 32) s += expf(row[v] - mx);
    #pragma unroll
    for (int o = 16; o; o >>= 1) s += __shfl_xor_sync(0xFFFFFFFFu, s, o);
    if (lane == 0) g_nll[warp] = logf(s) + mx - row[tgt[warp]];
}

__global__ void k_loss(float* __restrict__ out, int write_idx) {
    __shared__ float sh[256];
    float s = 0.f;
    for (int i = threadIdx.x; i < NT; i += 256) s += g_nll[i];
    sh[threadIdx.x] = s;
    __syncthreads();
    for (int o = 128; o; o >>= 1) {
        if (threadIdx.x < o) sh[threadIdx.x] += sh[threadIdx.x + o];
        __syncthreads();
    }
    if (threadIdx.x == 0) out[write_idx] = sh[0] / (float)NT;
}

// ---------- launch ----------
extern "C" void kernel_launch(void* const* d_in, const int* in_sizes, int n_in,
                              void* d_out, int out_size) {
    const int*   idx  = (const int*)  d_in[0];
    const int*   tgt  = (const int*)  d_in[1];
    const float* tok  = (const float*)d_in[2];
    const float* pos  = (const float*)d_in[3];
    const float* Wq   = (const float*)d_in[4];
    const float* Wk   = (const float*)d_in[5];
    const float* Wv   = (const float*)d_in[6];
    const float* Wo   = (const float*)d_in[7];
    const float* bo   = (const float*)d_in[8];
    const float* W1   = (const float*)d_in[9];
    const float* b1   = (const float*)d_in[10];
    const float* W2   = (const float*)d_in[11];
    const float* b2   = (const float*)d_in[12];
    const float* ln1g = (const float*)d_in[13];
    const float* ln1b = (const float*)d_in[14];
    const float* ln2g = (const float*)d_in[15];
    const float* ln2b = (const float*)d_in[16];
    const float* lnfg = (const float*)d_in[17];
    const float* lnfb = (const float*)d_in[18];
    const float* Wlm  = (const float*)d_in[19];
    const float* blm  = (const float*)d_in[20];
    float* out = (float*)d_out;

    float *px;
    __half *pa, *pan, *ph, *pw, *pqkvh;
    cudaGetSymbolAddress((void**)&px,    g_x);
    cudaGetSymbolAddress((void**)&pa,    g_a);
    cudaGetSymbolAddress((void**)&pan,   g_an);
    cudaGetSymbolAddress((void**)&ph,    g_h);
    cudaGetSymbolAddress((void**)&pqkvh, g_qkvh);
    cudaGetSymbolAddress((void**)&pw,    g_w);

    const int SMEM  = 3 * 32768;
    const int SMEML = 3 * 32768 + 1024;
    cudaFuncSetAttribute(k_hgemm<0,0>, cudaFuncAttributeMaxDynamicSharedMemorySize, SMEM);
    cudaFuncSetAttribute(k_hgemm<1,1>, cudaFuncAttributeMaxDynamicSharedMemorySize, SMEM);
    cudaFuncSetAttribute(k_hgemm_ln,   cudaFuncAttributeMaxDynamicSharedMemorySize, SMEML);
    cudaFuncSetAttribute(k_hgemm_lm,   cudaFuncAttributeMaxDynamicSharedMemorySize, SMEM);
    cudaFuncSetAttribute(k_fattn,      cudaFuncAttributeMaxDynamicSharedMemorySize, SMEM);

    // launch order: index 3 = QKV GEMM (ncu window)
    k_embed_ln<<<NT/8, 256>>>(idx, tok, pos, ln1g, ln1b);                     // 0
    k_wsplit_qkv<<<(LL*768*CC + 255)/256, 256>>>(Wq, Wk, Wv);                 // 1
    k_wsplit_all<<<(LL*LTOT + 255)/256, 256>>>(Wo, W1, W2);                   // 2
    k_hgemm<0,0><<<dim3(6, NT/128), 256, SMEM>>>(                             // 3
        pan, pw + W_QKV, nullptr, pqkvh, CC, 3*HQ);
    k_fattn<<<BB*HH, 256, SMEM>>>();                                          // 4
    k_wlmh<<<(128*CC + 255)/256, 256>>>(Wlm);                                 // 5

    for (int l = 0; l < LL; l++) {
        const __half* wl = pw + (size_t)l*WSZ;
        if (l > 0) {
            k_hgemm<0,0><<<dim3(6, NT/128), 256, SMEM>>>(
                pan, wl + W_QKV, nullptr, pqkvh, CC, 3*HQ);
            k_fattn<<<BB*HH, 256, SMEM>>>();
        }
        k_hgemm_ln<<<dim3(1, NT/128), 256, SMEML>>>(
            pa, wl + W_PROJ, bo + l*CC, px, pan, ln2g + l*CC, ln2b + l*CC, HQ);
        k_hgemm<1,1><<<dim3(12, NT/128), 256, SMEM>>>(
            pan, wl + W_FF1, b1 + l*FFF, ph, CC, FFF);
        const float* ng = (l + 1 < LL) ? ln1g + (l+1)*CC : lnfg;
        const float* nb = (l + 1 < LL) ? ln1b + (l+1)*CC : lnfb;
        k_hgemm_ln<<<dim3(1, NT/128), 256, SMEML>>>(
            ph, wl + W_FF2, b2 + l*CC, px, pan, ng, nb, FFF);
    }

    k_hgemm_lm<<<dim3(1, NT/128), 256, SMEM>>>(pan, blm, out);
    k_nll<<<NT/8, 256>>>(out, tgt);
    if (out_size == 1)         k_loss<<<1, 256>>>(out, 0);
    else if (out_size > NT*VV) k_loss<<<1, 256>>>(out, NT*VV);
}

// round 17
// speedup vs baseline: 1.3337x; 1.0767x over previous
#include <cuda_runtime.h>
#include <cuda_fp16.h>
#include <cstdint>
#include <math.h>

#define BB 128
#define TT 256
#define CC 384
#define HH 4
#define HSS 64
#define LL 6
#define VV 65
#define FFF 1536
#define NT (BB*TT)
#define HQ (HH*HSS)

#define WSZ 1572864
#define W_QKV 0
#define W_PROJ 294912
#define W_FF1 393216
#define W_FF2 983040

__device__ float g_x[NT*CC];
__device__ __half g_qkvh[NT*3*HQ];
__device__ __half g_a[NT*HQ];
__device__ __half g_an[NT*CC];
__device__ __half g_h[NT*FFF];
__device__ __half g_w[LL*WSZ];
__device__ __half g_wlmh[128*CC];
__device__ float g_rs[NT];       // per-row sum   (zero-init; k_lnq resets)
__device__ float g_rs2[NT];      // per-row sumsq
__device__ float g_nll[NT];

// ---------- PTX helpers ----------
__device__ __forceinline__ uint32_t s2u(const void* p) {
    uint32_t a;
    asm("{ .reg .u64 t; cvta.to.shared.u64 t, %1; cvt.u32.u64 %0, t; }" : "=r"(a) : "l"(p));
    return a;
}
#define CPA16(d,s) asm volatile("cp.async.cg.shared.global [%0], [%1], 16;" :: "r"(d), "l"(s))
#define CPCOMMIT() asm volatile("cp.async.commit_group;" ::: "memory")
#define CPWAIT0()  asm volatile("cp.async.wait_group 0;" ::: "memory")
#define CPWAIT1()  asm volatile("cp.async.wait_group 1;" ::: "memory")

#define LDSM4(r, a) \
    asm volatile("ldmatrix.sync.aligned.m8n8.x4.shared.b16 {%0,%1,%2,%3}, [%4];" \
        : "=r"((r)[0]), "=r"((r)[1]), "=r"((r)[2]), "=r"((r)[3]) : "r"(a))

#define LDSMT4(r, a) \
    asm volatile("ldmatrix.sync.aligned.m8n8.x4.trans.shared.b16 {%0,%1,%2,%3}, [%4];" \
        : "=r"((r)[0]), "=r"((r)[1]), "=r"((r)[2]), "=r"((r)[3]) : "r"(a))

#define MMAH16816(d, a, b0, b1) \
    asm volatile("mma.sync.aligned.m16n8k16.row.col.f32.f16.f16.f32 " \
        "{%0,%1,%2,%3}, {%4,%5,%6,%7}, {%8,%9}, {%0,%1,%2,%3};" \
        : "+f"((d)[0]), "+f"((d)[1]), "+f"((d)[2]), "+f"((d)[3]) \
        : "r"((a)[0]), "r"((a)[1]), "r"((a)[2]), "r"((a)[3]), "r"(b0), "r"(b1))

__device__ __forceinline__ uint32_t packh2(float a, float b) {
    __half2 h = __halves2half2(__float2half_rn(a), __float2half_rn(b));
    return *(uint32_t*)&h;
}

// ---------- shared GEMM building blocks ----------
__device__ __forceinline__ void load_chunk(uint32_t base, const __half* A, const __half* B,
                                           int K, int bm, int bn, int k0, int tid) {
    #pragma unroll
    for (int i = 0; i < 4; i++) {
        int u = tid + (i << 8);
        int row = u >> 3, kc = u & 7;
        uint32_t d = (uint32_t)(row*128) + ((((uint32_t)kc) ^ (uint32_t)(row & 7)) << 4);
        CPA16(base + d,          (const char*)(A + (size_t)(bm + row) * K + k0) + kc*16);
        CPA16(base + 16384u + d, (const char*)(B + (size_t)(bn + row) * K + k0) + kc*16);
    }
    CPCOMMIT();
}

__device__ __forceinline__ void compute_chunk(uint32_t ab, uint32_t bb,
                                              float (&acc)[4][4][4],
                                              int wm, int wn, int lr, int lh) {
    #pragma unroll
    for (int s = 0; s < 4; s++) {
        uint32_t Bf[2][4];
        #pragma unroll
        for (int bt = 0; bt < 2; bt++) {
            int row = wn*32 + bt*16 + lr;
            uint32_t d = (uint32_t)(row*128) +
                ((((uint32_t)(2*s + lh)) ^ (uint32_t)(row & 7)) << 4);
            LDSM4(Bf[bt], bb + d);
        }
        uint32_t Af[2][4];
        {
            int row = wm*64 + lr;
            uint32_t d = (uint32_t)(row*128) +
                ((((uint32_t)(2*s + lh)) ^ (uint32_t)(row & 7)) << 4);
            LDSM4(Af[0], ab + d);
        }
        #pragma unroll
        for (int mt = 0; mt < 4; mt++) {
            if (mt < 3) {
                int row = wm*64 + (mt+1)*16 + lr;
                uint32_t d = (uint32_t)(row*128) +
                    ((((uint32_t)(2*s + lh)) ^ (uint32_t)(row & 7)) << 4);
                LDSM4(Af[(mt+1) & 1], ab + d);
            }
            const uint32_t* Ac = Af[mt & 1];
            #pragma unroll
            for (int nt = 0; nt < 4; nt++) {
                int g = nt >> 1, j = nt & 1;
                MMAH16816(acc[mt][nt], Ac, Bf[g][j], Bf[g][j+2]);
            }
        }
    }
}

__device__ __forceinline__ void epi_resid(float (&acc)[4][4][4], const float* bias,
                                          float* px, float* rsum, float* rsum2,
                                          int bm, int bn, int wm, int wn, int lane) {
    const int r0 = lane >> 2, c2 = (lane & 3) * 2;
    #pragma unroll
    for (int mt = 0; mt < 4; mt++) {
        #pragma unroll
        for (int half = 0; half < 2; half++) {
            int rl = wm*64 + mt*16 + r0 + half*8;
            int m = bm + rl;
            float ps = 0.f, ps2 = 0.f;
            #pragma unroll
            for (int nt = 0; nt < 4; nt++) {
                int col = bn + wn*32 + nt*8 + c2;
                float v0 = acc[mt][nt][2*half]   + bias[col];
                float v1 = acc[mt][nt][2*half+1] + bias[col+1];
                float2 t = *(const float2*)(px + (size_t)m * CC + col);
                v0 += t.x; v1 += t.y;
                *(float2*)(px + (size_t)m * CC + col) = make_float2(v0, v1);
                ps  += v0 + v1;
                ps2 += v0*v0 + v1*v1;
                acc[mt][nt][2*half] = 0.f;
                acc[mt][nt][2*half+1] = 0.f;
            }
            ps  += __shfl_xor_sync(0xFFFFFFFFu, ps,  1);
            ps  += __shfl_xor_sync(0xFFFFFFFFu, ps,  2);
            ps2 += __shfl_xor_sync(0xFFFFFFFFu, ps2, 1);
            ps2 += __shfl_xor_sync(0xFFFFFFFFu, ps2, 2);
            if ((lane & 3) == 0) {
                atomicAdd(&rsum[rl], ps);
                atomicAdd(&rsum2[rl], ps2);
            }
        }
    }
}

__device__ __forceinline__ void ln_phase(const float* px, __half* oa,
                                         const float* rsum, const float* rsum2,
                                         const float* lng, const float* lnb,
                                         int bm, int w, int lane) {
    for (int rr = 0; rr < 16; rr++) {
        int rl = w*16 + rr;
        int m = bm + rl;
        float mu  = rsum[rl] * (1.f/CC);
        float var = rsum2[rl] * (1.f/CC) - mu*mu;
        float rst = rsqrtf(var + 1e-5f);
        #pragma unroll
        for (int i = 0; i < 3; i++) {
            int c = i*128 + lane*4;
            float4 v  = *(const float4*)(px + (size_t)m * CC + c);
            float4 gg = *(const float4*)(lng + c);
            float4 bb = *(const float4*)(lnb + c);
            *(__half2*)(oa + (size_t)m * CC + c)     = __halves2half2(
                __float2half_rn((v.x - mu)*rst*gg.x + bb.x),
                __float2half_rn((v.y - mu)*rst*gg.y + bb.y));
            *(__half2*)(oa + (size_t)m * CC + c + 2) = __halves2half2(
                __float2half_rn((v.z - mu)*rst*gg.z + bb.z),
                __float2half_rn((v.w - mu)*rst*gg.w + bb.w));
        }
    }
}

// ---------- fused embed + LN(layer0) ----------
__global__ void k_embed_ln(const int* __restrict__ idx, const float* __restrict__ tok,
                           const float* __restrict__ pos,
                           const float* __restrict__ g, const float* __restrict__ b) {
    int n = (blockIdx.x * blockDim.x + threadIdx.x) >> 5;
    int lane = threadIdx.x & 31;
    if (n >= NT) return;
    int t = n % TT;
    const float* trow = tok + (size_t)idx[n]*CC;
    const float* prow = pos + (size_t)t*CC;
    float e[12];
    float s = 0.f, s2 = 0.f;
    #pragma unroll
    for (int i = 0; i < 12; i++) {
        int c = lane + 32*i;
        e[i] = trow[c] + prow[c];
        s += e[i]; s2 += e[i]*e[i];
    }
    #pragma unroll
    for (int o = 16; o; o >>= 1) {
        s  += __shfl_xor_sync(0xFFFFFFFFu, s,  o);
        s2 += __shfl_xor_sync(0xFFFFFFFFu, s2, o);
    }
    float mu  = s  * (1.f/CC);
    float var = s2 * (1.f/CC) - mu*mu;
    float r   = rsqrtf(var + 1e-5f);
    size_t base = (size_t)n * CC;
    #pragma unroll
    for (int i = 0; i < 12; i++) {
        int c = lane + 32*i;
        g_x[base + c] = e[i];
        g_an[base + c] = __float2half_rn((e[i] - mu) * r * g[c] + b[c]);
    }
}

// ---------- weight setup ----------
__global__ void k_wsplit_qkv(const float* __restrict__ Wq, const float* __restrict__ Wk,
                             const float* __restrict__ Wv) {
    int i = blockIdx.x * blockDim.x + threadIdx.x;
    if (i >= LL*768*CC) return;
    int k = i % CC, n = (i / CC) % 768, l = i / (CC*768);
    const float* W = (n < HQ) ? Wq : (n < 2*HQ ? Wk : Wv);
    int nn = n % HQ, h = nn / HSS, d = nn % HSS;
    float v = W[(((size_t)l*HH + h)*CC + k)*HSS + d];
    g_w[(size_t)l*WSZ + W_QKV + (size_t)n*CC + k] = __float2half_rn(v);
}

#define PROJ_E (HQ*CC)
#define FF1_E  (CC*FFF)
#define LTOT   (PROJ_E + FF1_E + FF1_E)
__global__ void k_wsplit_all(const float* __restrict__ Wo, const float* __restrict__ W1,
                             const float* __restrict__ W2) {
    int i = blockIdx.x * blockDim.x + threadIdx.x;
    if (i >= LL*LTOT) return;
    int l = i / LTOT, r = i % LTOT;
    const float* W; int K, N, off;
    if (r < PROJ_E)              { W = Wo; K = HQ;  N = CC;  off = W_PROJ; }
    else if (r < PROJ_E + FF1_E) { W = W1; K = CC;  N = FFF; off = W_FF1;  r -= PROJ_E; }
    else                         { W = W2; K = FFF; N = CC;  off = W_FF2;  r -= PROJ_E + FF1_E; }
    int k = r % K, n = r / K;
    float v = W[((size_t)l*K + k)*N + n];
    g_w[(size_t)l*WSZ + off + (size_t)n*K + k] = __float2half_rn(v);
}

__global__ void k_wlmh(const float* __restrict__ Wlm) {
    int i = blockIdx.x * blockDim.x + threadIdx.x;
    if (i >= 128*CC) return;
    int v = i / CC, k = i % CC;
    g_wlmh[i] = (v < VV) ? __float2half_rn(Wlm[(size_t)k*VV + v]) : __float2half_rn(0.f);
}

// ---------- fp16 GEMM (QKV / FF1) ----------
template<int BIAS, int RELU>
__global__ __launch_bounds__(256, 2)
void k_hgemm(const __half* __restrict__ A, const __half* __restrict__ B,
             const float* __restrict__ bias, __half* __restrict__ oh,
             int K, int N) {
    extern __shared__ char sm[];
    const uint32_t smb = s2u(sm);
    const int tid = threadIdx.x, lane = tid & 31, w = tid >> 5;
    const int wm = w & 1, wn = w >> 1;
    const int bm = blockIdx.y * 128, bn = blockIdx.x * 128;
    const int nk = K >> 6;

    float acc[4][4][4];
    #pragma unroll
    for (int i = 0; i < 4; i++)
        #pragma unroll
        for (int j = 0; j < 4; j++)
            #pragma unroll
            for (int q = 0; q < 4; q++) acc[i][j][q] = 0.f;

    load_chunk(smb, A, B, K, bm, bn, 0, tid);
    if (nk > 1) load_chunk(smb + 32768u, A, B, K, bm, bn, 64, tid);

    const int lr = lane & 15, lh = lane >> 4;
    for (int c = 0; c < nk; c++) {
        if (c + 1 < nk) { CPWAIT1(); } else { CPWAIT0(); }
        __syncthreads();
        if (c + 2 < nk)
            load_chunk(smb + (uint32_t)((c + 2) % 3) * 32768u, A, B, K, bm, bn, (c+2) << 6, tid);
        const uint32_t ab = smb + (uint32_t)(c % 3) * 32768u;
        compute_chunk(ab, ab + 16384u, acc, wm, wn, lr, lh);
    }

    const int r0 = lane >> 2, c2 = (lane & 3) * 2;
    #pragma unroll
    for (int mt = 0; mt < 4; mt++) {
        #pragma unroll
        for (int nt = 0; nt < 4; nt++) {
            int col = bn + wn*32 + nt*8 + c2;
            #pragma unroll
            for (int half = 0; half < 2; half++) {
                int m = bm + wm*64 + mt*16 + r0 + half*8;
                float v0 = acc[mt][nt][2*half], v1 = acc[mt][nt][2*half + 1];
                if (BIAS)  { v0 += bias[col]; v1 += bias[col + 1]; }
                if (RELU)  { v0 = fmaxf(v0, 0.f); v1 = fmaxf(v1, 0.f); }
                *(__half2*)(oh + (size_t)m * N + col) =
                    __halves2half2(__float2half_rn(v0), __float2half_rn(v1));
            }
        }
    }
}

// ---------- FF2 plain GEMM + residual + global row sums ----------
__global__ __launch_bounds__(256, 2)
void k_hgemm_rs(const __half* __restrict__ A, const __half* __restrict__ B,
                const float* __restrict__ bias, float* __restrict__ px, int K) {
    extern __shared__ char sm[];
    const uint32_t smb = s2u(sm);
    const int tid = threadIdx.x, lane = tid & 31, w = tid >> 5;
    const int wm = w & 1, wn = w >> 1;
    const int bm = blockIdx.y * 128, bn = blockIdx.x * 128;
    const int nk = K >> 6;

    float acc[4][4][4];
    #pragma unroll
    for (int i = 0; i < 4; i++)
        #pragma unroll
        for (int j = 0; j < 4; j++)
            #pragma unroll
            for (int q = 0; q < 4; q++) acc[i][j][q] = 0.f;

    load_chunk(smb, A, B, K, bm, bn, 0, tid);
    if (nk > 1) load_chunk(smb + 32768u, A, B, K, bm, bn, 64, tid);

    const int lr = lane & 15, lh = lane >> 4;
    for (int c = 0; c < nk; c++) {
        if (c + 1 < nk) { CPWAIT1(); } else { CPWAIT0(); }
        __syncthreads();
        if (c + 2 < nk)
            load_chunk(smb + (uint32_t)((c + 2) % 3) * 32768u, A, B, K, bm, bn, (c+2) << 6, tid);
        const uint32_t ab = smb + (uint32_t)(c % 3) * 32768u;
        compute_chunk(ab, ab + 16384u, acc, wm, wn, lr, lh);
    }

    const int r0 = lane >> 2, c2 = (lane & 3) * 2;
    #pragma unroll
    for (int mt = 0; mt < 4; mt++) {
        #pragma unroll
        for (int half = 0; half < 2; half++) {
            int m = bm + wm*64 + mt*16 + r0 + half*8;
            float ps = 0.f, ps2 = 0.f;
            #pragma unroll
            for (int nt = 0; nt < 4; nt++) {
                int col = bn + wn*32 + nt*8 + c2;
                float v0 = acc[mt][nt][2*half]   + bias[col];
                float v1 = acc[mt][nt][2*half+1] + bias[col+1];
                float2 t = *(const float2*)(px + (size_t)m * CC + col);
                v0 += t.x; v1 += t.y;
                *(float2*)(px + (size_t)m * CC + col) = make_float2(v0, v1);
                ps  += v0 + v1;
                ps2 += v0*v0 + v1*v1;
            }
            ps  += __shfl_xor_sync(0xFFFFFFFFu, ps,  1);
            ps  += __shfl_xor_sync(0xFFFFFFFFu, ps,  2);
            ps2 += __shfl_xor_sync(0xFFFFFFFFu, ps2, 1);
            ps2 += __shfl_xor_sync(0xFFFFFFFFu, ps2, 2);
            if ((lane & 3) == 0) {
                atomicAdd(&g_rs[m], ps);
                atomicAdd(&g_rs2[m], ps2);
            }
        }
    }
}

// ---------- quick LN from precomputed sums; resets sums ----------
__global__ void k_lnq(const float* __restrict__ px, __half* __restrict__ oa,
                      const float* __restrict__ lng, const float* __restrict__ lnb) {
    int n = (blockIdx.x * blockDim.x + threadIdx.x) >> 5;
    int lane = threadIdx.x & 31;
    if (n >= NT) return;
    float mu  = g_rs[n]  * (1.f/CC);
    float var = g_rs2[n] * (1.f/CC) - mu*mu;
    float rst = rsqrtf(var + 1e-5f);
    size_t base = (size_t)n * CC;
    #pragma unroll
    for (int i = 0; i < 3; i++) {
        int c = i*128 + lane*4;
        float4 v  = *(const float4*)(px + base + c);
        float4 gg = *(const float4*)(lng + c);
        float4 bb = *(const float4*)(lnb + c);
        *(__half2*)(oa + base + c)     = __halves2half2(
            __float2half_rn((v.x - mu)*rst*gg.x + bb.x),
            __float2half_rn((v.y - mu)*rst*gg.y + bb.y));
        *(__half2*)(oa + base + c + 2) = __halves2half2(
            __float2half_rn((v.z - mu)*rst*gg.z + bb.z),
            __float2half_rn((v.w - mu)*rst*gg.w + bb.w));
    }
    if (lane == 0) { g_rs[n] = 0.f; g_rs2[n] = 0.f; }
}

// ---------- LM-head GEMM ----------
__global__ __launch_bounds__(256, 2)
void k_hgemm_lm(const __half* __restrict__ A, const float* __restrict__ blm,
                float* __restrict__ out) {
    extern __shared__ char sm[];
    const uint32_t smb = s2u(sm);
    const int tid = threadIdx.x, lane = tid & 31, w = tid >> 5;
    const int wm = w & 1, wn = w >> 1;
    const int bm = blockIdx.y * 128;
    const int nk = CC >> 6;

    float acc[4][4][4];
    #pragma unroll
    for (int i = 0; i < 4; i++)
        #pragma unroll
        for (int j = 0; j < 4; j++)
            #pragma unroll
            for (int q = 0; q < 4; q++) acc[i][j][q] = 0.f;

    load_chunk(smb, A, g_wlmh, CC, bm, 0, 0, tid);
    load_chunk(smb + 32768u, A, g_wlmh, CC, bm, 0, 64, tid);

    const int lr = lane & 15, lh = lane >> 4;
    for (int c = 0; c < nk; c++) {
        if (c + 1 < nk) { CPWAIT1(); } else { CPWAIT0(); }
        __syncthreads();
        if (c + 2 < nk)
            load_chunk(smb + (uint32_t)((c + 2) % 3) * 32768u, A, g_wlmh, CC,
                       bm, 0, (c+2) << 6, tid);
        const uint32_t ab = smb + (uint32_t)(c % 3) * 32768u;
        compute_chunk(ab, ab + 16384u, acc, wm, wn, lr, lh);
    }

    const int r0 = lane >> 2, c2 = (lane & 3) * 2;
    #pragma unroll
    for (int mt = 0; mt < 4; mt++) {
        #pragma unroll
        for (int nt = 0; nt < 4; nt++) {
            int col = wn*32 + nt*8 + c2;
            if (col >= VV) continue;
            #pragma unroll
            for (int half = 0; half < 2; half++) {
                int m = bm + wm*64 + mt*16 + r0 + half*8;
                float v0 = acc[mt][nt][2*half]     + blm[col];
                out[(size_t)m * VV + col] = v0;
                if (col + 1 < VV) {
                    float v1 = acc[mt][nt][2*half+1] + blm[col+1];
                    out[(size_t)m * VV + col + 1] = v1;
                }
            }
        }
    }
}

// ---------- fused GEMM + residual + LN (PROJ): N = 384, smem sums ----------
__global__ __launch_bounds__(256, 2)
void k_hgemm_ln(const __half* __restrict__ A, const __half* __restrict__ B,
                const float* __restrict__ bias, float* __restrict__ px,
                __half* __restrict__ oa,
                const float* __restrict__ lng, const float* __restrict__ lnb,
                int K) {
    extern __shared__ char sm[];
    const uint32_t smb = s2u(sm);
    float* rsum  = (float*)(sm + 98304);
    float* rsum2 = rsum + 128;
    const int tid = threadIdx.x, lane = tid & 31, w = tid >> 5;
    const int wm = w & 1, wn = w >> 1;
    const int bm = blockIdx.y * 128;
    const int nkc = K >> 6;
    const int total = 3 * nkc;

    if (tid < 128) { rsum[tid] = 0.f; rsum2[tid] = 0.f; }

    float acc[4][4][4];
    #pragma unroll
    for (int i = 0; i < 4; i++)
        #pragma unroll
        for (int j = 0; j < 4; j++)
            #pragma unroll
            for (int q = 0; q < 4; q++) acc[i][j][q] = 0.f;

    load_chunk(smb, A, B, K, bm, 0, 0, tid);
    load_chunk(smb + 32768u, A, B, K, bm, 0, 64, tid);

    const int lr = lane & 15, lh = lane >> 4;
    for (int cc = 0; cc < total; cc++) {
        if (cc + 1 < total) { CPWAIT1(); } else { CPWAIT0(); }
        __syncthreads();
        if (cc + 2 < total) {
            int nc = cc + 2;
            load_chunk(smb + (uint32_t)(nc % 3) * 32768u, A, B, K,
                       bm, (nc / nkc) * 128, (nc % nkc) << 6, tid);
        }
        const uint32_t ab = smb + (uint32_t)(cc % 3) * 32768u;
        compute_chunk(ab, ab + 16384u, acc, wm, wn, lr, lh);
        if ((cc + 1) % nkc == 0)
            epi_resid(acc, bias, px, rsum, rsum2, bm, (cc / nkc) * 128, wm, wn, lane);
    }

    __syncthreads();
    ln_phase(px, oa, rsum, rsum2, lng, lnb, bm, w, lane);
}

// ---------- tensor-core flash attention (two-chain) ----------
__global__ __launch_bounds__(256, 1)
void k_fattn() {
    extern __shared__ char sm[];
    const uint32_t smb = s2u(sm);
    const uint32_t Qb = smb, Kb = smb + 32768u, Vb = smb + 65536u;
    const int bh = blockIdx.x, bb = bh >> 2, hd = bh & 3;
    const int tid = threadIdx.x, lane = tid & 31, w = tid >> 5;

    const __half* src = g_qkvh + (size_t)(bb*TT)*768 + hd*HSS;
    #pragma unroll
    for (int i = 0; i < 8; i++) {
        int u = tid + (i << 8);
        int row = u >> 3, kc = u & 7;
        uint32_t d = (uint32_t)(row*128) + ((((uint32_t)kc) ^ (uint32_t)(row & 7)) << 4);
        const char* base = (const char*)(src + (size_t)row*768) + kc*16;
        CPA16(Qb + d, base);
        CPA16(Kb + d, base + 512);
        CPA16(Vb + d, base + 1024);
    }
    CPCOMMIT(); CPWAIT0();
    __syncthreads();

    const int lr = lane & 15, lh = lane >> 4;

    uint32_t Qf[2][4][4];
    #pragma unroll
    for (int mt = 0; mt < 2; mt++) {
        int row = w*32 + mt*16 + lr;
        uint32_t rb = Qb + (uint32_t)(row*128);
        uint32_t sel = (uint32_t)(row & 7);
        #pragma unroll
        for (int ks = 0; ks < 4; ks++)
            LDSM4(Qf[mt][ks], rb + ((((uint32_t)(2*ks + lh)) ^ sel) << 4));
    }
    {
        __half2 scl = __float2half2_rn(0.125f);
        #pragma unroll
        for (int mt = 0; mt < 2; mt++)
            #pragma unroll
            for (int ks = 0; ks < 4; ks++)
                #pragma unroll
                for (int j = 0; j < 4; j++) {
                    __half2 v = *(__half2*)&Qf[mt][ks][j];
                    v = __hmul2(v, scl);
                    Qf[mt][ks][j] = *(uint32_t*)&v;
                }
    }

    float O[2][8][4];
    #pragma unroll
    for (int mt = 0; mt < 2; mt++)
        #pragma unroll
        for (int nt = 0; nt < 8; nt++)
            #pragma unroll
            for (int q = 0; q < 4; q++) O[mt][nt][q] = 0.f;
    float mrow[2][2] = {{-1e30f,-1e30f},{-1e30f,-1e30f}};
    float lrow[2][2] = {{0.f,0.f},{0.f,0.f}};

    const int nch = (w >> 1) + 1;
    for (int cs = 0; cs < nch; cs++) {
        const bool diag = (cs == (w >> 1));
        #pragma unroll
        for (int mt = 0; mt < 2; mt++) {
            float S[8][4];
            #pragma unroll
            for (int nt = 0; nt < 8; nt++)
                #pragma unroll
                for (int q = 0; q < 4; q++) S[nt][q] = 0.f;
            #pragma unroll
            for (int bt = 0; bt < 4; bt++) {
                int srow = cs*64 + bt*16 + lr;
                uint32_t rb = Kb + (uint32_t)(srow*128);
                uint32_t sel = (uint32_t)(srow & 7);
                #pragma unroll
                for (int ks = 0; ks < 4; ks++) {
                    uint32_t Kf[4];
                    LDSM4(Kf, rb + ((((uint32_t)(2*ks + lh)) ^ sel) << 4));
                    MMAH16816(S[2*bt],   Qf[mt][ks], Kf[0], Kf[2]);
                    MMAH16816(S[2*bt+1], Qf[mt][ks], Kf[1], Kf[3]);
                }
            }
            const int rbase = w*32 + mt*16 + (lane >> 2);
            if (diag) {
                #pragma unroll
                for (int nt = 0; nt < 8; nt++) {
                    int col = cs*64 + nt*8 + 2*(lane & 3);
                    if (col     > rbase)     S[nt][0] = -1e30f;
                    if (col + 1 > rbase)     S[nt][1] = -1e30f;
                    if (col     > rbase + 8) S[nt][2] = -1e30f;
                    if (col + 1 > rbase + 8) S[nt][3] = -1e30f;
                }
            }
            #pragma unroll
            for (int h = 0; h < 2; h++) {
                float rmax = -1e30f;
                #pragma unroll
                for (int nt = 0; nt < 8; nt++)
                    rmax = fmaxf(rmax, fmaxf(S[nt][2*h], S[nt][2*h+1]));
                rmax = fmaxf(rmax, __shfl_xor_sync(0xFFFFFFFFu, rmax, 1));
                rmax = fmaxf(rmax, __shfl_xor_sync(0xFFFFFFFFu, rmax, 2));
                float mn = fmaxf(mrow[mt][h], rmax);
                float corr = __expf(mrow[mt][h] - mn);
                mrow[mt][h] = mn;
                float rsumv = 0.f;
                #pragma unroll
                for (int nt = 0; nt < 8; nt++) {
                    float e0 = __expf(S[nt][2*h]   - mn);
                    float e1 = __expf(S[nt][2*h+1] - mn);
                    S[nt][2*h] = e0; S[nt][2*h+1] = e1;
                    rsumv += e0 + e1;
                }
                rsumv += __shfl_xor_sync(0xFFFFFFFFu, rsumv, 1);
                rsumv += __shfl_xor_sync(0xFFFFFFFFu, rsumv, 2);
                lrow[mt][h] = lrow[mt][h]*corr + rsumv;
                #pragma unroll
                for (int nt = 0; nt < 8; nt++) {
                    O[mt][nt][2*h]   *= corr;
                    O[mt][nt][2*h+1] *= corr;
                }
            }
            #pragma unroll
            for (int ks = 0; ks < 4; ks++) {
                uint32_t Pf[4];
                Pf[0] = packh2(S[2*ks][0],   S[2*ks][1]);
                Pf[1] = packh2(S[2*ks][2],   S[2*ks][3]);
                Pf[2] = packh2(S[2*ks+1][0], S[2*ks+1][1]);
                Pf[3] = packh2(S[2*ks+1][2], S[2*ks+1][3]);
                int srow = cs*64 + ks*16 + lr;
                uint32_t rb = Vb + (uint32_t)(srow*128);
                uint32_t sel = (uint32_t)(srow & 7);
                #pragma unroll
                for (int dv = 0; dv < 4; dv++) {
                    uint32_t Vf[4];
                    LDSMT4(Vf, rb + ((((uint32_t)(2*dv + lh)) ^ sel) << 4));
                    MMAH16816(O[mt][2*dv],   Pf, Vf[0], Vf[1]);
                    MMAH16816(O[mt][2*dv+1], Pf, Vf[2], Vf[3]);
                }
            }
        }
    }
    #pragma unroll
    for (int mt = 0; mt < 2; mt++) {
        float inv0 = 1.f / lrow[mt][0];
        float inv1 = 1.f / lrow[mt][1];
        int r0 = w*32 + mt*16 + (lane >> 2);
        __half* d0 = g_a + (size_t)(bb*TT + r0)*HQ + hd*HSS + 2*(lane & 3);
        __half* d1 = d0 + 8*HQ;
        #pragma unroll
        for (int nt = 0; nt < 8; nt++) {
            *(__half2*)(d0 + nt*8) = __halves2half2(
                __float2half_rn(O[mt][nt][0]*inv0), __float2half_rn(O[mt][nt][1]*inv0));
            *(__half2*)(d1 + nt*8) = __halves2half2(
                __float2half_rn(O[mt][nt][2]*inv1), __float2half_rn(O[mt][nt][3]*inv1));
        }
    }
}

// ---------- NLL + loss ----------
__global__ void k_nll(const float* __restrict__ logits, const int* __restrict__ tgt) {
    int warp = (blockIdx.x * blockDim.x + threadIdx.x) >> 5;
    int lane = threadIdx.x & 31;
    if (warp >= NT) return;
    const float* row = logits + (size_t)warp * VV;
    float mx = -1e30f;
    for (int v = lane; v < VV; v += 32) mx = fmaxf(mx, row[v]);
    #pragma unroll
    for (int o = 16; o; o >>= 1) mx = fmaxf(mx, __shfl_xor_sync(0xFFFFFFFFu, mx, o));
    float s = 0.f;
    for (int v = lane; v < VV; v += 32) s += expf(row[v] - mx);
    #pragma unroll
    for (int o = 16; o; o >>= 1) s += __shfl_xor_sync(0xFFFFFFFFu, s, o);
    if (lane == 0) g_nll[warp] = logf(s) + mx - row[tgt[warp]];
}

__global__ void k_loss(float* __restrict__ out, int write_idx) {
    __shared__ float sh[256];
    float s = 0.f;
    for (int i = threadIdx.x; i < NT; i += 256) s += g_nll[i];
    sh[threadIdx.x] = s;
    __syncthreads();
    for (int o = 128; o; o >>= 1) {
        if (threadIdx.x < o) sh[threadIdx.x] += sh[threadIdx.x + o];
        __syncthreads();
    }
    if (threadIdx.x == 0) out[write_idx] = sh[0] / (float)NT;
}

// ---------- launch ----------
extern "C" void kernel_launch(void* const* d_in, const int* in_sizes, int n_in,
                              void* d_out, int out_size) {
    const int*   idx  = (const int*)  d_in[0];
    const int*   tgt  = (const int*)  d_in[1];
    const float* tok  = (const float*)d_in[2];
    const float* pos  = (const float*)d_in[3];
    const float* Wq   = (const float*)d_in[4];
    const float* Wk   = (const float*)d_in[5];
    const float* Wv   = (const float*)d_in[6];
    const float* Wo   = (const float*)d_in[7];
    const float* bo   = (const float*)d_in[8];
    const float* W1   = (const float*)d_in[9];
    const float* b1   = (const float*)d_in[10];
    const float* W2   = (const float*)d_in[11];
    const float* b2   = (const float*)d_in[12];
    const float* ln1g = (const float*)d_in[13];
    const float* ln1b = (const float*)d_in[14];
    const float* ln2g = (const float*)d_in[15];
    const float* ln2b = (const float*)d_in[16];
    const float* lnfg = (const float*)d_in[17];
    const float* lnfb = (const float*)d_in[18];
    const float* Wlm  = (const float*)d_in[19];
    const float* blm  = (const float*)d_in[20];
    float* out = (float*)d_out;

    float *px;
    __half *pa, *pan, *ph, *pw, *pqkvh;
    cudaGetSymbolAddress((void**)&px,    g_x);
    cudaGetSymbolAddress((void**)&pa,    g_a);
    cudaGetSymbolAddress((void**)&pan,   g_an);
    cudaGetSymbolAddress((void**)&ph,    g_h);
    cudaGetSymbolAddress((void**)&pqkvh, g_qkvh);
    cudaGetSymbolAddress((void**)&pw,    g_w);

    const int SMEM  = 3 * 32768;
    const int SMEML = 3 * 32768 + 1024;
    cudaFuncSetAttribute(k_hgemm<0,0>, cudaFuncAttributeMaxDynamicSharedMemorySize, SMEM);
    cudaFuncSetAttribute(k_hgemm<1,1>, cudaFuncAttributeMaxDynamicSharedMemorySize, SMEM);
    cudaFuncSetAttribute(k_hgemm_rs,   cudaFuncAttributeMaxDynamicSharedMemorySize, SMEM);
    cudaFuncSetAttribute(k_hgemm_ln,   cudaFuncAttributeMaxDynamicSharedMemorySize, SMEML);
    cudaFuncSetAttribute(k_hgemm_lm,   cudaFuncAttributeMaxDynamicSharedMemorySize, SMEM);
    cudaFuncSetAttribute(k_fattn,      cudaFuncAttributeMaxDynamicSharedMemorySize, SMEM);

    // launch order: index 3 = QKV GEMM (ncu window)
    k_embed_ln<<<NT/8, 256>>>(idx, tok, pos, ln1g, ln1b);                     // 0
    k_wsplit_qkv<<<(LL*768*CC + 255)/256, 256>>>(Wq, Wk, Wv);                 // 1
    k_wsplit_all<<<(LL*LTOT + 255)/256, 256>>>(Wo, W1, W2);                   // 2
    k_hgemm<0,0><<<dim3(6, NT/128), 256, SMEM>>>(                             // 3
        pan, pw + W_QKV, nullptr, pqkvh, CC, 3*HQ);
    k_fattn<<<BB*HH, 256, SMEM>>>();                                          // 4
    k_wlmh<<<(128*CC + 255)/256, 256>>>(Wlm);                                 // 5

    for (int l = 0; l < LL; l++) {
        const __half* wl = pw + (size_t)l*WSZ;
        if (l > 0) {
            k_hgemm<0,0><<<dim3(6, NT/128), 256, SMEM>>>(
                pan, wl + W_QKV, nullptr, pqkvh, CC, 3*HQ);
            k_fattn<<<BB*HH, 256, SMEM>>>();
        }
        // PROJ + residual + LN2 (fused, smem sums)
        k_hgemm_ln<<<dim3(1, NT/128), 256, SMEML>>>(
            pa, wl + W_PROJ, bo + l*CC, px, pan, ln2g + l*CC, ln2b + l*CC, HQ);
        // FF1 + bias + relu
        k_hgemm<1,1><<<dim3(12, NT/128), 256, SMEM>>>(
            pan, wl + W_FF1, b1 + l*FFF, ph, CC, FFF);
        // FF2: plain grid GEMM + residual + global row sums, then quick LN
        k_hgemm_rs<<<dim3(3, NT/128), 256, SMEM>>>(
            ph, wl + W_FF2, b2 + l*CC, px, FFF);
        const float* ng = (l + 1 < LL) ? ln1g + (l+1)*CC : lnfg;
        const float* nb = (l + 1 < LL) ? ln1b + (l+1)*CC : lnfb;
        k_lnq<<<NT/8, 256>>>(px, pan, ng, nb);
    }

    k_hgemm_lm<<<dim3(1, NT/128), 256, SMEM>>>(pan, blm, out);
    k_nll<<<NT/8, 256>>>(out, tgt);
    if (out_size == 1)         k_loss<<<1, 256>>>(out, 0);
    else if (out_size > NT*VV) k_loss<<<1, 256>>>(out, NT*VV);
}